// round 7
// baseline (speedup 1.0000x reference)
#include <cuda_runtime.h>
#include <cuda_fp16.h>
#include <math.h>
#include <stdint.h>

#define Bc     8
#define Nc     1000
#define Dc     64
#define ADc    32
#define NEc    4000      // E * N
#define ACOLS  8000      // 2 * E * N
#define KCH    32        // K per chunk
#define NCHUNK 125       // 4000 / 32
#define ASTR   40        // A smem stride (halves)
#define BSTR   72        // B smem stride (halves)

// Scratch (static device globals; no allocation)
__device__ __half g_Ah[(size_t)Bc * Nc * ACOLS];   // fp16 copy of A (128 MB)
__device__ __half g_sh[2][Bc][NEc][Dc];            // S (fp16), k-major rows
__device__ float  g_a[2][Bc][Nc][Dc];              // a_in / a_out
__device__ float  g_state[2][Bc][Nc][Dc];          // s1 / s2
__device__ float  g_P[Bc * Nc][192];               // GRU pre-activations
__device__ float  g_rs[Bc * Nc][Dc];               // r * state
__device__ float  g_WT[192][192];                  // [k][out]: r|z|h (h state-cols zeroed)
__device__ float  g_Wh2T[Dc][Dc];                  // [k][f] = W_h[f][128+k]

// ---------------------------------------------------------------------------
// helpers
// ---------------------------------------------------------------------------
__device__ __forceinline__ void cp_async16(uint32_t dst, const void* src) {
    asm volatile("cp.async.cg.shared.global [%0], [%1], 16;\n" :: "r"(dst), "l"(src));
}
__device__ __forceinline__ void cp_commit() {
    asm volatile("cp.async.commit_group;\n");
}
__device__ __forceinline__ void ldm4(uint32_t* r, uint32_t addr) {
    asm volatile("ldmatrix.sync.aligned.m8n8.x4.shared.b16 {%0,%1,%2,%3}, [%4];"
                 : "=r"(r[0]), "=r"(r[1]), "=r"(r[2]), "=r"(r[3]) : "r"(addr));
}
__device__ __forceinline__ void ldm4t(uint32_t* r, uint32_t addr) {
    asm volatile("ldmatrix.sync.aligned.m8n8.x4.trans.shared.b16 {%0,%1,%2,%3}, [%4];"
                 : "=r"(r[0]), "=r"(r[1]), "=r"(r[2]), "=r"(r[3]) : "r"(addr));
}
__device__ __forceinline__ void mma_f16(float* c, const uint32_t* a,
                                        uint32_t b0, uint32_t b1) {
    asm volatile("mma.sync.aligned.m16n8k16.row.col.f32.f16.f16.f32 "
                 "{%0,%1,%2,%3},{%4,%5,%6,%7},{%8,%9},{%0,%1,%2,%3};"
                 : "+f"(c[0]), "+f"(c[1]), "+f"(c[2]), "+f"(c[3])
                 : "r"(a[0]), "r"(a[1]), "r"(a[2]), "r"(a[3]), "r"(b0), "r"(b1));
}

// ---------------------------------------------------------------------------
// A fp32 -> fp16 (one pass)
// ---------------------------------------------------------------------------
__global__ void __launch_bounds__(256) k_convA(const float* __restrict__ A) {
    size_t idx = (size_t)blockIdx.x * 256 + threadIdx.x;
    float4 v = ((const float4*)A)[idx];
    __half2 h0 = __floats2half2_rn(v.x, v.y);
    __half2 h1 = __floats2half2_rn(v.z, v.w);
    ((uint2*)g_Ah)[idx] = make_uint2(*(uint32_t*)&h0, *(uint32_t*)&h1);
}

// ---------------------------------------------------------------------------
// One-time weight transposes for the GRU GEMMs
// ---------------------------------------------------------------------------
__global__ void __launch_bounds__(256) k_prepW(const float* __restrict__ W_r,
                                               const float* __restrict__ W_z,
                                               const float* __restrict__ W_h) {
    int idx = blockIdx.x * 256 + threadIdx.x;
    if (idx < 192 * 192) {
        int k = idx / 192, out = idx % 192;
        int grp = out >> 6, f = out & 63;
        const float* W = (grp == 0) ? W_r : (grp == 1) ? W_z : W_h;
        float v = W[f * 192 + k];
        if (grp == 2 && k >= 128) v = 0.f;
        g_WT[k][out] = v;
    }
    if (idx < 64 * 64) {
        int k = idx / 64, f = idx % 64;
        g_Wh2T[k][f] = W_h[f * 192 + 128 + k];
    }
}

// ---------------------------------------------------------------------------
// s projection (tiled GEMM) -> fp16 S, k-major rows
// grid (125, 8), block 256.
// ---------------------------------------------------------------------------
__global__ void __launch_bounds__(256) k_compute_s2(
    const float* __restrict__ Xext, int use_ext,
    const float* __restrict__ W_in, const float* __restrict__ W_out) {
    const float* X = use_ext ? Xext : &g_state[0][0][0][0];
    int rb = blockIdx.x, cb = blockIdx.y;
    __shared__ float x_sm[64][64];
    __shared__ float wT[64][64];
    int t = threadIdx.x;

#pragma unroll
    for (int i = 0; i < 4; i++) {
        int idx = i * 256 + t;
        int r = idx >> 4, c4 = idx & 15;
        int gr = rb * 64 + r;
        *(float4*)&x_sm[r][c4 * 4] = *(const float4*)&X[(size_t)gr * 64 + c4 * 4];
    }
    const float* Wsrc = (cb < 4) ? (W_in + (size_t)cb * 64 * 64)
                                 : (W_out + (size_t)(cb - 4) * 64 * 64);
#pragma unroll
    for (int i = 0; i < 4; i++) {
        int idx = i * 256 + t;
        int cl = idx >> 4, k4 = idx & 15;
        float4 v = *(const float4*)&Wsrc[cl * 64 + k4 * 4];
        wT[k4 * 4 + 0][cl] = v.x;
        wT[k4 * 4 + 1][cl] = v.y;
        wT[k4 * 4 + 2][cl] = v.z;
        wT[k4 * 4 + 3][cl] = v.w;
    }
    __syncthreads();

    int ty = t >> 5, tx = t & 31;
    float acc[8][2];
#pragma unroll
    for (int i = 0; i < 8; i++) { acc[i][0] = 0.f; acc[i][1] = 0.f; }

#pragma unroll
    for (int k4 = 0; k4 < 16; k4++) {
        float4 xv[8];
#pragma unroll
        for (int i = 0; i < 8; i++) xv[i] = *(float4*)&x_sm[ty * 8 + i][k4 * 4];
#pragma unroll
        for (int q = 0; q < 4; q++) {
            float2 wv = *(float2*)&wT[k4 * 4 + q][tx * 2];
#pragma unroll
            for (int i = 0; i < 8; i++) {
                float xs = (q == 0) ? xv[i].x : (q == 1) ? xv[i].y
                         : (q == 2) ? xv[i].z : xv[i].w;
                acc[i][0] += xs * wv.x;
                acc[i][1] += xs * wv.y;
            }
        }
    }

    int cbase = cb * 64 + tx * 2;
    int half = cbase >> 8, e = (cbase >> 6) & 3, f = cbase & 63;
#pragma unroll
    for (int i = 0; i < 8; i++) {
        int gr = rb * 64 + ty * 8 + i;
        int b = gr / 1000, n = gr % 1000;
        __half2 hv = __floats2half2_rn(acc[i][0], acc[i][1]);
        *(__half2*)&g_sh[half][b][e * 1000 + n][f] = hv;
    }
}

// ---------------------------------------------------------------------------
// Big adjacency GEMM, fp16 mma + ldmatrix, cp.async 4-stage pipeline
// grid (8, 2, 8), 256 threads (8 warps: 4m x 2n, warp tile 32x32).
// ---------------------------------------------------------------------------
__global__ void __launch_bounds__(256) k_biggemm_f16(int dummy) {
    __shared__ __half Asm[4][128 * ASTR];
    __shared__ __half Bsm[4][32 * BSTR];

    int rb = blockIdx.x, half = blockIdx.y, b = blockIdx.z;
    int row0 = rb * 128;
    const __half* Abh = g_Ah + (size_t)b * Nc * ACOLS + (size_t)half * NEc;
    const __half* Sbh = &g_sh[half][b][0][0];

    int t = threadIdx.x, lane = t & 31, warp = t >> 5;
    int wm = warp & 3, wn = warp >> 2;

    const __half* asrc[2]; uint32_t adst[2];
#pragma unroll
    for (int j = 0; j < 2; j++) {
        int flat = j * 256 + t;
        int row = flat >> 2, seg = flat & 3;
        int gr = row0 + row; if (gr > Nc - 1) gr = Nc - 1;
        asrc[j] = Abh + (size_t)gr * ACOLS + seg * 8;
        adst[j] = (uint32_t)(row * ASTR + seg * 8) * 2u;
    }
    int brow = t >> 3, bseg = t & 7;
    const __half* bsrc = Sbh + (size_t)brow * Dc + bseg * 8;
    uint32_t bdst = (uint32_t)(brow * BSTR + bseg * 8) * 2u;

    uint32_t a_base[4], b_base[4];
#pragma unroll
    for (int s = 0; s < 4; s++) {
        a_base[s] = (uint32_t)__cvta_generic_to_shared(&Asm[s][0]);
        b_base[s] = (uint32_t)__cvta_generic_to_shared(&Bsm[s][0]);
    }

    uint32_t a_off[2][2];
#pragma unroll
    for (int mt = 0; mt < 2; mt++)
#pragma unroll
        for (int kk = 0; kk < 2; kk++) {
            int row = wm * 32 + mt * 16 + ((lane >> 3) & 1) * 8 + (lane & 7);
            int col = kk * 16 + (lane >> 4) * 8;
            a_off[mt][kk] = (uint32_t)(row * ASTR + col) * 2u;
        }
    uint32_t b_off[2][2];
#pragma unroll
    for (int g = 0; g < 2; g++)
#pragma unroll
        for (int kk = 0; kk < 2; kk++) {
            int krow = kk * 16 + (lane & 15);
            int ncol = wn * 32 + g * 16 + (lane >> 4) * 8;
            b_off[g][kk] = (uint32_t)(krow * BSTR + ncol) * 2u;
        }

    float acc[2][4][4];
#pragma unroll
    for (int mt = 0; mt < 2; mt++)
#pragma unroll
        for (int nt = 0; nt < 4; nt++)
#pragma unroll
            for (int c = 0; c < 4; c++) acc[mt][nt][c] = 0.f;

#pragma unroll
    for (int ch = 0; ch < 3; ch++) {
        int kt = ch * KCH;
#pragma unroll
        for (int j = 0; j < 2; j++) cp_async16(a_base[ch] + adst[j], asrc[j] + kt);
        cp_async16(b_base[ch] + bdst, bsrc + (size_t)kt * Dc);
        cp_commit();
    }

    for (int i = 0; i < NCHUNK; i++) {
        asm volatile("cp.async.wait_group 2;\n");
        __syncthreads();

        if (i + 3 < NCHUNK) {
            int s = (i + 3) & 3;
            int kt = (i + 3) * KCH;
#pragma unroll
            for (int j = 0; j < 2; j++) cp_async16(a_base[s] + adst[j], asrc[j] + kt);
            cp_async16(b_base[s] + bdst, bsrc + (size_t)kt * Dc);
        }
        cp_commit();

        uint32_t ab = a_base[i & 3], bb = b_base[i & 3];
        uint32_t aF[2][2][4];
        uint32_t bF[2][2][4];
#pragma unroll
        for (int kk = 0; kk < 2; kk++)
#pragma unroll
            for (int mt = 0; mt < 2; mt++) ldm4(aF[kk][mt], ab + a_off[mt][kk]);
#pragma unroll
        for (int kk = 0; kk < 2; kk++)
#pragma unroll
            for (int g = 0; g < 2; g++) ldm4t(bF[kk][g], bb + b_off[g][kk]);

#pragma unroll
        for (int kk = 0; kk < 2; kk++)
#pragma unroll
            for (int mt = 0; mt < 2; mt++)
#pragma unroll
                for (int nt = 0; nt < 4; nt++) {
                    int g = nt >> 1, sel = nt & 1;
                    mma_f16(acc[mt][nt], aF[kk][mt],
                            bF[kk][g][sel * 2], bF[kk][g][sel * 2 + 1]);
                }
    }

    float (*C)[Dc] = g_a[half][b];
#pragma unroll
    for (int mt = 0; mt < 2; mt++) {
        int r_a = row0 + wm * 32 + mt * 16 + (lane >> 2);
        int r_b = r_a + 8;
#pragma unroll
        for (int nt = 0; nt < 4; nt++) {
            int col = wn * 32 + nt * 8 + (lane & 3) * 2;
            if (r_a < Nc) *(float2*)&C[r_a][col] = make_float2(acc[mt][nt][0], acc[mt][nt][1]);
            if (r_b < Nc) *(float2*)&C[r_b][col] = make_float2(acc[mt][nt][2], acc[mt][nt][3]);
        }
    }
}

// ---------------------------------------------------------------------------
// GRU GEMM 1: P(8000x192) = [a_in | a_out | state] @ WT
// grid (125, 3), block 256. K chunks = the three 64-wide segments.
// ---------------------------------------------------------------------------
__global__ void __launch_bounds__(256) k_gruA(const float* __restrict__ ext_state,
                                              int use_ext) {
    int rb = blockIdx.x, cb = blockIdx.y;
    __shared__ float x_sm[64][64];
    __shared__ float w_sm[64][64];
    int t = threadIdx.x;
    int ty = t >> 5, tx = t & 31;

    float acc[8][2];
#pragma unroll
    for (int i = 0; i < 8; i++) { acc[i][0] = 0.f; acc[i][1] = 0.f; }

    for (int kc = 0; kc < 3; kc++) {
        // load X chunk (64 rows x 64 k)
#pragma unroll
        for (int i = 0; i < 4; i++) {
            int idx = i * 256 + t;
            int r = idx >> 4, c4 = idx & 15;
            int gr = rb * 64 + r;
            int b = gr / 1000, n = gr % 1000;
            float4 v;
            if (kc == 0)      v = *(const float4*)&g_a[0][b][n][c4 * 4];
            else if (kc == 1) v = *(const float4*)&g_a[1][b][n][c4 * 4];
            else {
                const float* sp = use_ext ? (ext_state + (size_t)gr * 64)
                                          : &g_state[0][b][n][0];
                v = *(const float4*)&sp[c4 * 4];
            }
            *(float4*)&x_sm[r][c4 * 4] = v;
        }
        // load W chunk: w_sm[k][ol] = g_WT[kc*64+k][cb*64+ol]
#pragma unroll
        for (int i = 0; i < 4; i++) {
            int idx = i * 256 + t;
            int k = idx >> 4, ol4 = idx & 15;
            *(float4*)&w_sm[k][ol4 * 4] =
                *(const float4*)&g_WT[kc * 64 + k][cb * 64 + ol4 * 4];
        }
        __syncthreads();

#pragma unroll
        for (int k4 = 0; k4 < 16; k4++) {
            float4 xv[8];
#pragma unroll
            for (int i = 0; i < 8; i++) xv[i] = *(float4*)&x_sm[ty * 8 + i][k4 * 4];
#pragma unroll
            for (int q = 0; q < 4; q++) {
                float2 wv = *(float2*)&w_sm[k4 * 4 + q][tx * 2];
#pragma unroll
                for (int i = 0; i < 8; i++) {
                    float xs = (q == 0) ? xv[i].x : (q == 1) ? xv[i].y
                             : (q == 2) ? xv[i].z : xv[i].w;
                    acc[i][0] += xs * wv.x;
                    acc[i][1] += xs * wv.y;
                }
            }
        }
        __syncthreads();
    }

#pragma unroll
    for (int i = 0; i < 8; i++) {
        int gr = rb * 64 + ty * 8 + i;
        *(float2*)&g_P[gr][cb * 64 + tx * 2] = make_float2(acc[i][0], acc[i][1]);
    }
}

// ---------------------------------------------------------------------------
// GRU elementwise: rs = sigmoid(P_r) * state
// grid 500, block 256; one float4 per thread (8000*16 float4s).
// ---------------------------------------------------------------------------
__global__ void __launch_bounds__(256) k_gruB(const float* __restrict__ ext_state,
                                              int use_ext) {
    int idx = blockIdx.x * 256 + threadIdx.x;   // 0 .. 127999
    int bn = idx >> 4, c4 = idx & 15;
    float4 p = *(const float4*)&g_P[bn][c4 * 4];
    const float* sp = use_ext ? (ext_state + (size_t)bn * 64)
                              : (&g_state[0][0][0][0] + (size_t)bn * 64);
    float4 st = *(const float4*)&sp[c4 * 4];
    float4 o;
    o.x = st.x / (1.f + expf(-p.x));
    o.y = st.y / (1.f + expf(-p.y));
    o.z = st.z / (1.f + expf(-p.z));
    o.w = st.w / (1.f + expf(-p.w));
    *(float4*)&g_rs[bn][c4 * 4] = o;
}

// ---------------------------------------------------------------------------
// GRU GEMM 2 + gate epilogue:
//   H2 = rs @ Wh2T; h = tanh(P_h + H2); z = sigm(P_z);
//   newstate = (1-z)*state + z*h
// grid 125, block 256.
// ---------------------------------------------------------------------------
__global__ void __launch_bounds__(256) k_gruC(const float* __restrict__ ext_state,
                                              int use_ext, int out_idx) {
    int rb = blockIdx.x;
    __shared__ float x_sm[64][64];
    __shared__ float w_sm[64][64];
    int t = threadIdx.x;
    int ty = t >> 5, tx = t & 31;

#pragma unroll
    for (int i = 0; i < 4; i++) {
        int idx = i * 256 + t;
        int r = idx >> 4, c4 = idx & 15;
        int gr = rb * 64 + r;
        *(float4*)&x_sm[r][c4 * 4] = *(const float4*)&g_rs[gr][c4 * 4];
    }
#pragma unroll
    for (int i = 0; i < 4; i++) {
        int idx = i * 256 + t;
        int k = idx >> 4, f4 = idx & 15;
        *(float4*)&w_sm[k][f4 * 4] = *(const float4*)&g_Wh2T[k][f4 * 4];
    }
    __syncthreads();

    float acc[8][2];
#pragma unroll
    for (int i = 0; i < 8; i++) { acc[i][0] = 0.f; acc[i][1] = 0.f; }

#pragma unroll
    for (int k4 = 0; k4 < 16; k4++) {
        float4 xv[8];
#pragma unroll
        for (int i = 0; i < 8; i++) xv[i] = *(float4*)&x_sm[ty * 8 + i][k4 * 4];
#pragma unroll
        for (int q = 0; q < 4; q++) {
            float2 wv = *(float2*)&w_sm[k4 * 4 + q][tx * 2];
#pragma unroll
            for (int i = 0; i < 8; i++) {
                float xs = (q == 0) ? xv[i].x : (q == 1) ? xv[i].y
                         : (q == 2) ? xv[i].z : xv[i].w;
                acc[i][0] += xs * wv.x;
                acc[i][1] += xs * wv.y;
            }
        }
    }

    int f = tx * 2;
#pragma unroll
    for (int i = 0; i < 8; i++) {
        int gr = rb * 64 + ty * 8 + i;
        int b = gr / 1000, n = gr % 1000;
        float2 pz = *(float2*)&g_P[gr][64 + f];
        float2 ph = *(float2*)&g_P[gr][128 + f];
        const float* sp = use_ext ? (ext_state + (size_t)gr * 64)
                                  : &g_state[0][b][n][0];
        float2 st = *(float2*)&sp[f];
        float z0 = 1.f / (1.f + expf(-pz.x));
        float z1 = 1.f / (1.f + expf(-pz.y));
        float h0 = tanhf(ph.x + acc[i][0]);
        float h1 = tanhf(ph.y + acc[i][1]);
        float2 o = make_float2((1.f - z0) * st.x + z0 * h0,
                               (1.f - z1) * st.y + z1 * h1);
        *(float2*)&g_state[out_idx][b][n][f] = o;
    }
}

// ---------------------------------------------------------------------------
// out[b,n] = sum_f tanh( sum_{j<96} [s2|annot][j] * Wo1[f,j] ) * Wo2[f]
// ---------------------------------------------------------------------------
__global__ void k_final(const float* __restrict__ annotation,
                        const float* __restrict__ Wo1,
                        const float* __restrict__ Wo2,
                        float* __restrict__ out) {
    __shared__ float join[4][96];
    __shared__ float terms[4][64];
    int t = threadIdx.x;
    int base = blockIdx.x * 4;

    for (int idx = t; idx < 4 * 96; idx += 256) {
        int lr = idx / 96, j = idx % 96;
        int bn = base + lr;
        int b = bn / Nc, n = bn % Nc;
        join[lr][j] = (j < Dc) ? g_state[1][b][n][j]
                               : annotation[(size_t)bn * ADc + (j - Dc)];
    }
    __syncthreads();

    int f = t & 63, q = t >> 6;
    const float4* w = (const float4*)(Wo1 + (size_t)f * 96);
    float acc = 0.f;
#pragma unroll
    for (int j4 = 0; j4 < 24; j4++) {
        float4 wv = w[j4];
        float4 jv = *(float4*)&join[q][j4 * 4];
        acc += wv.x * jv.x + wv.y * jv.y + wv.z * jv.z + wv.w * jv.w;
    }
    terms[q][f] = tanhf(acc) * Wo2[f];
    __syncthreads();

    if (f == 0) {
        float s = 0.f;
#pragma unroll
        for (int i = 0; i < Dc; i++) s += terms[q][i];
        out[base + q] = s;
    }
}

// ---------------------------------------------------------------------------
extern "C" void kernel_launch(void* const* d_in, const int* in_sizes, int n_in,
                              void* d_out, int out_size) {
    const float* prop_state = (const float*)d_in[0];
    const float* annotation = (const float*)d_in[1];
    const float* A          = (const float*)d_in[2];
    const float* W_in       = (const float*)d_in[3];
    const float* W_out      = (const float*)d_in[4];
    const float* W_r        = (const float*)d_in[5];
    const float* W_z        = (const float*)d_in[6];
    const float* W_h        = (const float*)d_in[7];
    const float* Wo1        = (const float*)d_in[8];
    const float* Wo2        = (const float*)d_in[9];
    float* out = (float*)d_out;

    dim3 s_grid(125, 8);
    dim3 gemm_grid(8, 2, Bc);
    dim3 gruA_grid(125, 3);

    k_convA<<<Bc * Nc * ACOLS / 4 / 256, 256>>>(A);
    k_prepW<<<144, 256>>>(W_r, W_z, W_h);

    // ---- propagate step 1 (state = prop_state) ----
    k_compute_s2<<<s_grid, 256>>>(prop_state, 1, W_in, W_out);
    k_biggemm_f16<<<gemm_grid, 256>>>(0);
    k_gruA<<<gruA_grid, 256>>>(prop_state, 1);
    k_gruB<<<500, 256>>>(prop_state, 1);
    k_gruC<<<125, 256>>>(prop_state, 1, 0);

    // ---- propagate step 2 (state = g_state[0]) ----
    k_compute_s2<<<s_grid, 256>>>(nullptr, 0, W_in, W_out);
    k_biggemm_f16<<<gemm_grid, 256>>>(0);
    k_gruA<<<gruA_grid, 256>>>(nullptr, 0);
    k_gruB<<<500, 256>>>(nullptr, 0);
    k_gruC<<<125, 256>>>(nullptr, 0, 1);

    // ---- output head ----
    k_final<<<Bc * Nc / 4, 256>>>(annotation, Wo1, Wo2, out);
}

// round 8
// speedup vs baseline: 1.4853x; 1.4853x over previous
#include <cuda_runtime.h>
#include <cuda_fp16.h>
#include <math.h>
#include <stdint.h>

#define Bc     8
#define Nc     1000
#define Dc     64
#define ADc    32
#define NEc    4000      // E * N
#define ACOLS  8000      // 2 * E * N
#define KCH    32        // K per chunk
#define NCHUNK 125       // 4000 / 32
#define ASTR   40        // A smem stride (halves)
#define BSTR   72        // B smem stride (halves)

// Scratch (static device globals; no allocation)
__device__ __half g_Ah[(size_t)Bc * Nc * ACOLS];   // fp16 copy of A (128 MB)
__device__ __half g_sh[2][Bc][NEc][Dc];            // S (fp16), k-major rows
__device__ float  g_a[2][Bc][Nc][Dc];              // a_in / a_out
__device__ float  g_state[2][Bc][Nc][Dc];          // s1 / s2
__device__ float  g_P[Bc * Nc][192];               // GRU pre-activations
__device__ float  g_WT[192][192];                  // [k][out]: r|z|h (h state-cols zeroed)
__device__ float  g_Wh2T[Dc][Dc];                  // [k][f] = W_h[f][128+k]

// ---------------------------------------------------------------------------
// helpers
// ---------------------------------------------------------------------------
__device__ __forceinline__ void cp_async16(uint32_t dst, const void* src) {
    asm volatile("cp.async.cg.shared.global [%0], [%1], 16;\n" :: "r"(dst), "l"(src));
}
__device__ __forceinline__ void cp_commit() {
    asm volatile("cp.async.commit_group;\n");
}
__device__ __forceinline__ void ldm4(uint32_t* r, uint32_t addr) {
    asm volatile("ldmatrix.sync.aligned.m8n8.x4.shared.b16 {%0,%1,%2,%3}, [%4];"
                 : "=r"(r[0]), "=r"(r[1]), "=r"(r[2]), "=r"(r[3]) : "r"(addr));
}
__device__ __forceinline__ void ldm4t(uint32_t* r, uint32_t addr) {
    asm volatile("ldmatrix.sync.aligned.m8n8.x4.trans.shared.b16 {%0,%1,%2,%3}, [%4];"
                 : "=r"(r[0]), "=r"(r[1]), "=r"(r[2]), "=r"(r[3]) : "r"(addr));
}
__device__ __forceinline__ void mma_f16(float* c, const uint32_t* a,
                                        uint32_t b0, uint32_t b1) {
    asm volatile("mma.sync.aligned.m16n8k16.row.col.f32.f16.f16.f32 "
                 "{%0,%1,%2,%3},{%4,%5,%6,%7},{%8,%9},{%0,%1,%2,%3};"
                 : "+f"(c[0]), "+f"(c[1]), "+f"(c[2]), "+f"(c[3])
                 : "r"(a[0]), "r"(a[1]), "r"(a[2]), "r"(a[3]), "r"(b0), "r"(b1));
}

// ---------------------------------------------------------------------------
// A fp32 -> fp16 (one pass)
// ---------------------------------------------------------------------------
__global__ void __launch_bounds__(256) k_convA(const float* __restrict__ A) {
    size_t idx = (size_t)blockIdx.x * 256 + threadIdx.x;
    float4 v = ((const float4*)A)[idx];
    __half2 h0 = __floats2half2_rn(v.x, v.y);
    __half2 h1 = __floats2half2_rn(v.z, v.w);
    ((uint2*)g_Ah)[idx] = make_uint2(*(uint32_t*)&h0, *(uint32_t*)&h1);
}

// ---------------------------------------------------------------------------
// One-time weight transposes for the GRU GEMMs
// ---------------------------------------------------------------------------
__global__ void __launch_bounds__(256) k_prepW(const float* __restrict__ W_r,
                                               const float* __restrict__ W_z,
                                               const float* __restrict__ W_h) {
    int idx = blockIdx.x * 256 + threadIdx.x;
    if (idx < 192 * 192) {
        int k = idx / 192, out = idx % 192;
        int grp = out >> 6, f = out & 63;
        const float* W = (grp == 0) ? W_r : (grp == 1) ? W_z : W_h;
        float v = W[f * 192 + k];
        if (grp == 2 && k >= 128) v = 0.f;
        g_WT[k][out] = v;
    }
    if (idx < 64 * 64) {
        int k = idx / 64, f = idx % 64;
        g_Wh2T[k][f] = W_h[f * 192 + 128 + k];
    }
}

// ---------------------------------------------------------------------------
// s projection (tiled GEMM) -> fp16 S, k-major rows
// grid (125, 8), block 256.
// ---------------------------------------------------------------------------
__global__ void __launch_bounds__(256) k_compute_s2(
    const float* __restrict__ Xext, int use_ext,
    const float* __restrict__ W_in, const float* __restrict__ W_out) {
    const float* X = use_ext ? Xext : &g_state[0][0][0][0];
    int rb = blockIdx.x, cb = blockIdx.y;
    __shared__ float x_sm[64][64];
    __shared__ float wT[64][64];
    int t = threadIdx.x;

#pragma unroll
    for (int i = 0; i < 4; i++) {
        int idx = i * 256 + t;
        int r = idx >> 4, c4 = idx & 15;
        int gr = rb * 64 + r;
        *(float4*)&x_sm[r][c4 * 4] = *(const float4*)&X[(size_t)gr * 64 + c4 * 4];
    }
    const float* Wsrc = (cb < 4) ? (W_in + (size_t)cb * 64 * 64)
                                 : (W_out + (size_t)(cb - 4) * 64 * 64);
#pragma unroll
    for (int i = 0; i < 4; i++) {
        int idx = i * 256 + t;
        int cl = idx >> 4, k4 = idx & 15;
        float4 v = *(const float4*)&Wsrc[cl * 64 + k4 * 4];
        wT[k4 * 4 + 0][cl] = v.x;
        wT[k4 * 4 + 1][cl] = v.y;
        wT[k4 * 4 + 2][cl] = v.z;
        wT[k4 * 4 + 3][cl] = v.w;
    }
    __syncthreads();

    int ty = t >> 5, tx = t & 31;
    float acc[8][2];
#pragma unroll
    for (int i = 0; i < 8; i++) { acc[i][0] = 0.f; acc[i][1] = 0.f; }

#pragma unroll
    for (int k4 = 0; k4 < 16; k4++) {
        float4 xv[8];
#pragma unroll
        for (int i = 0; i < 8; i++) xv[i] = *(float4*)&x_sm[ty * 8 + i][k4 * 4];
#pragma unroll
        for (int q = 0; q < 4; q++) {
            float2 wv = *(float2*)&wT[k4 * 4 + q][tx * 2];
#pragma unroll
            for (int i = 0; i < 8; i++) {
                float xs = (q == 0) ? xv[i].x : (q == 1) ? xv[i].y
                         : (q == 2) ? xv[i].z : xv[i].w;
                acc[i][0] += xs * wv.x;
                acc[i][1] += xs * wv.y;
            }
        }
    }

    int cbase = cb * 64 + tx * 2;
    int half = cbase >> 8, e = (cbase >> 6) & 3, f = cbase & 63;
#pragma unroll
    for (int i = 0; i < 8; i++) {
        int gr = rb * 64 + ty * 8 + i;
        int b = gr / 1000, n = gr % 1000;
        __half2 hv = __floats2half2_rn(acc[i][0], acc[i][1]);
        *(__half2*)&g_sh[half][b][e * 1000 + n][f] = hv;
    }
}

// ---------------------------------------------------------------------------
// Big adjacency GEMM, fp16 mma + ldmatrix, cp.async 4-stage pipeline.
// M=64 CTA tile for occupancy: grid (16, 2, 8) = 256 CTAs, 128 threads
// (4 warps; warp tile 16m x 64n). smem 39 KB -> ~4 CTAs/SM.
// ---------------------------------------------------------------------------
__global__ void __launch_bounds__(128) k_biggemm_f16(int dummy) {
    __shared__ __half Asm[4][64 * ASTR];   // 4 x 5120 B
    __shared__ __half Bsm[4][32 * BSTR];   // 4 x 4608 B

    int rb = blockIdx.x, half = blockIdx.y, b = blockIdx.z;
    int row0 = rb * 64;
    const __half* Abh = g_Ah + (size_t)b * Nc * ACOLS + (size_t)half * NEc;
    const __half* Sbh = &g_sh[half][b][0][0];

    int t = threadIdx.x, lane = t & 31, warp = t >> 5;

    // cp.async mappings (2 x 16B per thread for each operand)
    const __half* asrc[2]; uint32_t adst[2];
#pragma unroll
    for (int j = 0; j < 2; j++) {
        int flat = j * 128 + t;
        int row = flat >> 2, seg = flat & 3;           // 64 rows x 4 x 16B
        int gr = row0 + row; if (gr > Nc - 1) gr = Nc - 1;
        asrc[j] = Abh + (size_t)gr * ACOLS + seg * 8;
        adst[j] = (uint32_t)(row * ASTR + seg * 8) * 2u;
    }
    const __half* bsrc[2]; uint32_t bdst[2];
#pragma unroll
    for (int j = 0; j < 2; j++) {
        int flat = j * 128 + t;
        int row = flat >> 3, seg = flat & 7;           // 32 rows x 8 x 16B
        bsrc[j] = Sbh + (size_t)row * Dc + seg * 8;
        bdst[j] = (uint32_t)(row * BSTR + seg * 8) * 2u;
    }

    uint32_t a_base[4], b_base[4];
#pragma unroll
    for (int s = 0; s < 4; s++) {
        a_base[s] = (uint32_t)__cvta_generic_to_shared(&Asm[s][0]);
        b_base[s] = (uint32_t)__cvta_generic_to_shared(&Bsm[s][0]);
    }

    // ldmatrix offsets
    uint32_t a_off[2];      // [kk]
#pragma unroll
    for (int kk = 0; kk < 2; kk++) {
        int row = warp * 16 + ((lane >> 3) & 1) * 8 + (lane & 7);
        int col = kk * 16 + (lane >> 4) * 8;
        a_off[kk] = (uint32_t)(row * ASTR + col) * 2u;
    }
    uint32_t b_off[4][2];   // [g][kk]  (trans: rows k, cols n)
#pragma unroll
    for (int g = 0; g < 4; g++)
#pragma unroll
        for (int kk = 0; kk < 2; kk++) {
            int krow = kk * 16 + (lane & 15);
            int ncol = g * 16 + (lane >> 4) * 8;
            b_off[g][kk] = (uint32_t)(krow * BSTR + ncol) * 2u;
        }

    float acc[8][4];
#pragma unroll
    for (int nt = 0; nt < 8; nt++)
#pragma unroll
        for (int c = 0; c < 4; c++) acc[nt][c] = 0.f;

    // prologue: chunks 0..2
#pragma unroll
    for (int ch = 0; ch < 3; ch++) {
        int kt = ch * KCH;
#pragma unroll
        for (int j = 0; j < 2; j++) {
            cp_async16(a_base[ch] + adst[j], asrc[j] + kt);
            cp_async16(b_base[ch] + bdst[j], bsrc[j] + (size_t)kt * Dc);
        }
        cp_commit();
    }

    for (int i = 0; i < NCHUNK; i++) {
        asm volatile("cp.async.wait_group 2;\n");
        __syncthreads();

        if (i + 3 < NCHUNK) {
            int s = (i + 3) & 3;
            int kt = (i + 3) * KCH;
#pragma unroll
            for (int j = 0; j < 2; j++) {
                cp_async16(a_base[s] + adst[j], asrc[j] + kt);
                cp_async16(b_base[s] + bdst[j], bsrc[j] + (size_t)kt * Dc);
            }
        }
        cp_commit();

        uint32_t ab = a_base[i & 3], bb = b_base[i & 3];
        uint32_t aF[2][4];       // [kk]
        uint32_t bF[2][4][4];    // [kk][g]
#pragma unroll
        for (int kk = 0; kk < 2; kk++) ldm4(aF[kk], ab + a_off[kk]);
#pragma unroll
        for (int kk = 0; kk < 2; kk++)
#pragma unroll
            for (int g = 0; g < 4; g++) ldm4t(bF[kk][g], bb + b_off[g][kk]);

#pragma unroll
        for (int kk = 0; kk < 2; kk++)
#pragma unroll
            for (int nt = 0; nt < 8; nt++) {
                int g = nt >> 1, sel = nt & 1;
                mma_f16(acc[nt], aF[kk],
                        bF[kk][g][sel * 2], bF[kk][g][sel * 2 + 1]);
            }
    }

    // epilogue
    float (*C)[Dc] = g_a[half][b];
    int r_a = row0 + warp * 16 + (lane >> 2);
    int r_b = r_a + 8;
#pragma unroll
    for (int nt = 0; nt < 8; nt++) {
        int col = nt * 8 + (lane & 3) * 2;
        if (r_a < Nc) *(float2*)&C[r_a][col] = make_float2(acc[nt][0], acc[nt][1]);
        if (r_b < Nc) *(float2*)&C[r_b][col] = make_float2(acc[nt][2], acc[nt][3]);
    }
}

// ---------------------------------------------------------------------------
// GRU GEMM 1: P(8000x192) = [a_in | a_out | state] @ WT
// grid (125, 3), block 256. K chunks = the three 64-wide segments.
// ---------------------------------------------------------------------------
__global__ void __launch_bounds__(256) k_gruA(const float* __restrict__ ext_state,
                                              int use_ext) {
    int rb = blockIdx.x, cb = blockIdx.y;
    __shared__ float x_sm[64][64];
    __shared__ float w_sm[64][64];
    int t = threadIdx.x;
    int ty = t >> 5, tx = t & 31;

    float acc[8][2];
#pragma unroll
    for (int i = 0; i < 8; i++) { acc[i][0] = 0.f; acc[i][1] = 0.f; }

    for (int kc = 0; kc < 3; kc++) {
#pragma unroll
        for (int i = 0; i < 4; i++) {
            int idx = i * 256 + t;
            int r = idx >> 4, c4 = idx & 15;
            int gr = rb * 64 + r;
            int b = gr / 1000, n = gr % 1000;
            float4 v;
            if (kc == 0)      v = *(const float4*)&g_a[0][b][n][c4 * 4];
            else if (kc == 1) v = *(const float4*)&g_a[1][b][n][c4 * 4];
            else {
                const float* sp = use_ext ? (ext_state + (size_t)gr * 64)
                                          : &g_state[0][b][n][0];
                v = *(const float4*)&sp[c4 * 4];
            }
            *(float4*)&x_sm[r][c4 * 4] = v;
        }
#pragma unroll
        for (int i = 0; i < 4; i++) {
            int idx = i * 256 + t;
            int k = idx >> 4, ol4 = idx & 15;
            *(float4*)&w_sm[k][ol4 * 4] =
                *(const float4*)&g_WT[kc * 64 + k][cb * 64 + ol4 * 4];
        }
        __syncthreads();

#pragma unroll
        for (int k4 = 0; k4 < 16; k4++) {
            float4 xv[8];
#pragma unroll
            for (int i = 0; i < 8; i++) xv[i] = *(float4*)&x_sm[ty * 8 + i][k4 * 4];
#pragma unroll
            for (int q = 0; q < 4; q++) {
                float2 wv = *(float2*)&w_sm[k4 * 4 + q][tx * 2];
#pragma unroll
                for (int i = 0; i < 8; i++) {
                    float xs = (q == 0) ? xv[i].x : (q == 1) ? xv[i].y
                             : (q == 2) ? xv[i].z : xv[i].w;
                    acc[i][0] += xs * wv.x;
                    acc[i][1] += xs * wv.y;
                }
            }
        }
        __syncthreads();
    }

#pragma unroll
    for (int i = 0; i < 8; i++) {
        int gr = rb * 64 + ty * 8 + i;
        *(float2*)&g_P[gr][cb * 64 + tx * 2] = make_float2(acc[i][0], acc[i][1]);
    }
}

// ---------------------------------------------------------------------------
// GRU GEMM 2 + gate epilogue (rs computed inline from P_r and state):
//   rs = sigm(P_r)*state; H2 = rs @ Wh2T; h = tanh(P_h + H2);
//   z = sigm(P_z); newstate = (1-z)*state + z*h
// grid 125, block 256.
// ---------------------------------------------------------------------------
__global__ void __launch_bounds__(256) k_gruC(const float* __restrict__ ext_state,
                                              int use_ext, int out_idx) {
    int rb = blockIdx.x;
    __shared__ float x_sm[64][64];
    __shared__ float w_sm[64][64];
    int t = threadIdx.x;
    int ty = t >> 5, tx = t & 31;

    // x_sm = rs = sigmoid(P_r) * state
#pragma unroll
    for (int i = 0; i < 4; i++) {
        int idx = i * 256 + t;
        int r = idx >> 4, c4 = idx & 15;
        int gr = rb * 64 + r;
        int b = gr / 1000, n = gr % 1000;
        float4 p = *(const float4*)&g_P[gr][c4 * 4];
        const float* sp = use_ext ? (ext_state + (size_t)gr * 64)
                                  : &g_state[0][b][n][0];
        float4 st = *(const float4*)&sp[c4 * 4];
        float4 o;
        o.x = st.x / (1.f + expf(-p.x));
        o.y = st.y / (1.f + expf(-p.y));
        o.z = st.z / (1.f + expf(-p.z));
        o.w = st.w / (1.f + expf(-p.w));
        *(float4*)&x_sm[r][c4 * 4] = o;
    }
#pragma unroll
    for (int i = 0; i < 4; i++) {
        int idx = i * 256 + t;
        int k = idx >> 4, f4 = idx & 15;
        *(float4*)&w_sm[k][f4 * 4] = *(const float4*)&g_Wh2T[k][f4 * 4];
    }
    __syncthreads();

    float acc[8][2];
#pragma unroll
    for (int i = 0; i < 8; i++) { acc[i][0] = 0.f; acc[i][1] = 0.f; }

#pragma unroll
    for (int k4 = 0; k4 < 16; k4++) {
        float4 xv[8];
#pragma unroll
        for (int i = 0; i < 8; i++) xv[i] = *(float4*)&x_sm[ty * 8 + i][k4 * 4];
#pragma unroll
        for (int q = 0; q < 4; q++) {
            float2 wv = *(float2*)&w_sm[k4 * 4 + q][tx * 2];
#pragma unroll
            for (int i = 0; i < 8; i++) {
                float xs = (q == 0) ? xv[i].x : (q == 1) ? xv[i].y
                         : (q == 2) ? xv[i].z : xv[i].w;
                acc[i][0] += xs * wv.x;
                acc[i][1] += xs * wv.y;
            }
        }
    }

    int f = tx * 2;
#pragma unroll
    for (int i = 0; i < 8; i++) {
        int gr = rb * 64 + ty * 8 + i;
        int b = gr / 1000, n = gr % 1000;
        float2 pz = *(float2*)&g_P[gr][64 + f];
        float2 ph = *(float2*)&g_P[gr][128 + f];
        const float* sp = use_ext ? (ext_state + (size_t)gr * 64)
                                  : &g_state[0][b][n][0];
        float2 st = *(float2*)&sp[f];
        float z0 = 1.f / (1.f + expf(-pz.x));
        float z1 = 1.f / (1.f + expf(-pz.y));
        float h0 = tanhf(ph.x + acc[i][0]);
        float h1 = tanhf(ph.y + acc[i][1]);
        float2 o = make_float2((1.f - z0) * st.x + z0 * h0,
                               (1.f - z1) * st.y + z1 * h1);
        *(float2*)&g_state[out_idx][b][n][f] = o;
    }
}

// ---------------------------------------------------------------------------
// out[b,n] = sum_f tanh( sum_{j<96} [s2|annot][j] * Wo1[f,j] ) * Wo2[f]
// ---------------------------------------------------------------------------
__global__ void k_final(const float* __restrict__ annotation,
                        const float* __restrict__ Wo1,
                        const float* __restrict__ Wo2,
                        float* __restrict__ out) {
    __shared__ float join[4][96];
    __shared__ float terms[4][64];
    int t = threadIdx.x;
    int base = blockIdx.x * 4;

    for (int idx = t; idx < 4 * 96; idx += 256) {
        int lr = idx / 96, j = idx % 96;
        int bn = base + lr;
        int b = bn / Nc, n = bn % Nc;
        join[lr][j] = (j < Dc) ? g_state[1][b][n][j]
                               : annotation[(size_t)bn * ADc + (j - Dc)];
    }
    __syncthreads();

    int f = t & 63, q = t >> 6;
    const float4* w = (const float4*)(Wo1 + (size_t)f * 96);
    float acc = 0.f;
#pragma unroll
    for (int j4 = 0; j4 < 24; j4++) {
        float4 wv = w[j4];
        float4 jv = *(float4*)&join[q][j4 * 4];
        acc += wv.x * jv.x + wv.y * jv.y + wv.z * jv.z + wv.w * jv.w;
    }
    terms[q][f] = tanhf(acc) * Wo2[f];
    __syncthreads();

    if (f == 0) {
        float s = 0.f;
#pragma unroll
        for (int i = 0; i < Dc; i++) s += terms[q][i];
        out[base + q] = s;
    }
}

// ---------------------------------------------------------------------------
extern "C" void kernel_launch(void* const* d_in, const int* in_sizes, int n_in,
                              void* d_out, int out_size) {
    const float* prop_state = (const float*)d_in[0];
    const float* annotation = (const float*)d_in[1];
    const float* A          = (const float*)d_in[2];
    const float* W_in       = (const float*)d_in[3];
    const float* W_out      = (const float*)d_in[4];
    const float* W_r        = (const float*)d_in[5];
    const float* W_z        = (const float*)d_in[6];
    const float* W_h        = (const float*)d_in[7];
    const float* Wo1        = (const float*)d_in[8];
    const float* Wo2        = (const float*)d_in[9];
    float* out = (float*)d_out;

    dim3 s_grid(125, 8);
    dim3 gemm_grid(16, 2, Bc);
    dim3 gruA_grid(125, 3);

    k_convA<<<Bc * Nc * ACOLS / 4 / 256, 256>>>(A);
    k_prepW<<<144, 256>>>(W_r, W_z, W_h);

    // ---- propagate step 1 (state = prop_state) ----
    k_compute_s2<<<s_grid, 256>>>(prop_state, 1, W_in, W_out);
    k_biggemm_f16<<<gemm_grid, 128>>>(0);
    k_gruA<<<gruA_grid, 256>>>(prop_state, 1);
    k_gruC<<<125, 256>>>(prop_state, 1, 0);

    // ---- propagate step 2 (state = g_state[0]) ----
    k_compute_s2<<<s_grid, 256>>>(nullptr, 0, W_in, W_out);
    k_biggemm_f16<<<gemm_grid, 128>>>(0);
    k_gruA<<<gruA_grid, 256>>>(nullptr, 0);
    k_gruC<<<125, 256>>>(nullptr, 0, 1);

    // ---- output head ----
    k_final<<<Bc * Nc / 4, 256>>>(annotation, Wo1, Wo2, out);
}